// round 1
// baseline (speedup 1.0000x reference)
#include <cuda_runtime.h>
#include <math.h>

#define Bsz   2
#define Slen  2048
#define Hdim  1024
#define NHn   16
#define HDn   64
#define Mtot  (Bsz*Slen)   // 4096
#define EPSf  1e-12f

// -------- scratch (no allocations allowed) --------
__device__ float g_q[Mtot*Hdim];
__device__ float g_k[Mtot*Hdim];
__device__ float g_v[Mtot*Hdim];
__device__ float g_ctx[Mtot*Hdim];
__device__ float g_y[Mtot*Hdim];

// ============================================================
// C[M,N] = A[M,1024] @ W[N,1024]^T + bias, two epilogues:
//   headLayout=1 : scatter to [B,NH,S,HD] layout (QKV path)
//   headLayout=0 : out[m*H+n] = val + bias[n] + res[m*H+n] (O-proj + residual)
// Tiles: BM=BN=64, BK=16, 256 threads, 4x4 per thread.
// ============================================================
__global__ void gemm_kernel(const float* __restrict__ A, const float* __restrict__ W,
                            const float* __restrict__ bias, const float* __restrict__ res,
                            float* __restrict__ out, int headLayout)
{
    __shared__ float As[16][64];
    __shared__ float Bs[16][64];

    const int tid = threadIdx.x;               // 0..255
    const int n0  = blockIdx.x * 64;
    const int m0  = blockIdx.y * 64;
    const int tm  = (tid >> 4) * 4;            // 0..60
    const int tn  = (tid & 15) * 4;            // 0..60
    const int lr  = tid >> 2;                  // 0..63 (tile row to load)
    const int lk  = (tid & 3) * 4;             // 0,4,8,12

    float acc[4][4];
#pragma unroll
    for (int i = 0; i < 4; i++)
#pragma unroll
        for (int j = 0; j < 4; j++) acc[i][j] = 0.f;

    for (int k0 = 0; k0 < Hdim; k0 += 16) {
        float4 a4 = *(const float4*)(A + (size_t)(m0 + lr) * Hdim + k0 + lk);
        float4 b4 = *(const float4*)(W + (size_t)(n0 + lr) * Hdim + k0 + lk);
        As[lk + 0][lr] = a4.x; As[lk + 1][lr] = a4.y;
        As[lk + 2][lr] = a4.z; As[lk + 3][lr] = a4.w;
        Bs[lk + 0][lr] = b4.x; Bs[lk + 1][lr] = b4.y;
        Bs[lk + 2][lr] = b4.z; Bs[lk + 3][lr] = b4.w;
        __syncthreads();

#pragma unroll
        for (int kk = 0; kk < 16; kk++) {
            float4 ar = *(const float4*)&As[kk][tm];
            float4 br = *(const float4*)&Bs[kk][tn];
            float a[4] = {ar.x, ar.y, ar.z, ar.w};
            float b[4] = {br.x, br.y, br.z, br.w};
#pragma unroll
            for (int i = 0; i < 4; i++)
#pragma unroll
                for (int j = 0; j < 4; j++) acc[i][j] += a[i] * b[j];
        }
        __syncthreads();
    }

    if (headLayout) {
#pragma unroll
        for (int i = 0; i < 4; i++) {
            const int m = m0 + tm + i;
            const int b = m >> 11;         // /Slen
            const int s = m & (Slen - 1);
#pragma unroll
            for (int j = 0; j < 4; j++) {
                const int n = n0 + tn + j;
                const int h = n >> 6;
                const int d = n & 63;
                out[(((size_t)(b * NHn + h) * Slen) + s) * HDn + d] = acc[i][j] + bias[n];
            }
        }
    } else {
#pragma unroll
        for (int i = 0; i < 4; i++) {
            const int m = m0 + tm + i;
#pragma unroll
            for (int j = 0; j < 4; j++) {
                const int n = n0 + tn + j;
                out[(size_t)m * Hdim + n] = acc[i][j] + bias[n] + res[(size_t)m * Hdim + n];
            }
        }
    }
}

// ============================================================
// Causal flash attention, fp32. Q/K/V in [B,NH,S,HD] layout.
// Block = 64 threads = 64 query rows; K/V tiles of 64 keys in smem.
// Q tile transposed+XOR-swizzled in smem -> conflict-free per-thread column.
// ctx written back in [B,S,H] layout for the O-proj GEMM.
// ============================================================
__global__ void attn_kernel(const float* __restrict__ Q, const float* __restrict__ K,
                            const float* __restrict__ V, float* __restrict__ ctx)
{
    __shared__ float qs[64 * 64];
    __shared__ float ks[64 * 64];
    __shared__ float vs[64 * 64];

    const int t  = threadIdx.x;          // 0..63
    const int qt = blockIdx.x;           // query tile
    const int h  = blockIdx.y;
    const int b  = blockIdx.z;
    const int m0 = qt * 64;
    const int m  = m0 + t;               // this thread's query row

    const size_t base = (size_t)(b * NHn + h) * Slen * HDn;
    const float* Qb = Q + base;
    const float* Kb = K + base;
    const float* Vb = V + base;

    // load Q tile transposed: element (d=t, row=i) at slot t*64 + (i ^ (t&31))
    for (int i = 0; i < 64; i++)
        qs[t * 64 + (i ^ (t & 31))] = Qb[(size_t)(m0 + i) * HDn + t];

    float acc[64];
#pragma unroll
    for (int d = 0; d < 64; d++) acc[d] = 0.f;
    float m_i = -1e30f, l = 0.f;
    float sc[64];

    for (int kt = 0; kt <= qt; kt++) {
        const int k0 = kt * 64;
        __syncthreads();
        for (int i = 0; i < 64; i++) {
            ks[i * 64 + t] = Kb[(size_t)(k0 + i) * HDn + t];
            vs[i * 64 + t] = Vb[(size_t)(k0 + i) * HDn + t];
        }
        __syncthreads();

        // scores
#pragma unroll 1
        for (int kk = 0; kk < 64; kk++) {
            float s = 0.f;
#pragma unroll
            for (int d = 0; d < 64; d++)
                s += qs[d * 64 + (t ^ (d & 31))] * ks[kk * 64 + d];
            sc[kk] = (k0 + kk <= m) ? s * 0.125f : -1e30f;
        }

        // online softmax
        float mx = m_i;
#pragma unroll 1
        for (int kk = 0; kk < 64; kk++) mx = fmaxf(mx, sc[kk]);
        const float corr = __expf(m_i - mx);
        l *= corr;
#pragma unroll
        for (int d = 0; d < 64; d++) acc[d] *= corr;
#pragma unroll 1
        for (int kk = 0; kk < 64; kk++) {
            const float p = __expf(sc[kk] - mx);
            l += p;
#pragma unroll
            for (int d = 0; d < 64; d++) acc[d] += p * vs[kk * 64 + d];
        }
        m_i = mx;
    }

    const float inv = 1.f / l;
    float* outp = ctx + ((size_t)(b * Slen + m)) * Hdim + h * HDn;
#pragma unroll
    for (int d = 0; d < 64; d++) outp[d] = acc[d] * inv;
}

// ============================================================
// Row LayerNorm over H=1024; one block (256 thr, float4) per row.
// ============================================================
__global__ void ln_kernel(const float* __restrict__ y, const float* __restrict__ g,
                          const float* __restrict__ be, float* __restrict__ out)
{
    __shared__ float red[256];
    const int row = blockIdx.x;
    const int tid = threadIdx.x;
    const float4 v = ((const float4*)(y + (size_t)row * Hdim))[tid];

    float sum = v.x + v.y + v.z + v.w;
    red[tid] = sum; __syncthreads();
    for (int s = 128; s > 0; s >>= 1) {
        if (tid < s) red[tid] += red[tid + s];
        __syncthreads();
    }
    const float mu = red[0] * (1.f / 1024.f);
    __syncthreads();

    const float d0 = v.x - mu, d1 = v.y - mu, d2 = v.z - mu, d3 = v.w - mu;
    red[tid] = d0 * d0 + d1 * d1 + d2 * d2 + d3 * d3; __syncthreads();
    for (int s = 128; s > 0; s >>= 1) {
        if (tid < s) red[tid] += red[tid + s];
        __syncthreads();
    }
    const float inv = rsqrtf(red[0] * (1.f / 1024.f) + EPSf);

    const float4 gg = ((const float4*)g)[tid];
    const float4 bb = ((const float4*)be)[tid];
    float4 o;
    o.x = d0 * inv * gg.x + bb.x;
    o.y = d1 * inv * gg.y + bb.y;
    o.z = d2 * inv * gg.z + bb.z;
    o.w = d3 * inv * gg.w + bb.w;
    ((float4*)(out + (size_t)row * Hdim))[tid] = o;
}

// ============================================================
extern "C" void kernel_launch(void* const* d_in, const int* in_sizes, int n_in,
                              void* d_out, int out_size)
{
    const float* x    = (const float*)d_in[0];
    const float* Wq   = (const float*)d_in[1];
    const float* bq   = (const float*)d_in[2];
    const float* Wk   = (const float*)d_in[3];
    const float* bk   = (const float*)d_in[4];
    const float* Wv   = (const float*)d_in[5];
    const float* bv   = (const float*)d_in[6];
    const float* Wo   = (const float*)d_in[7];
    const float* bo   = (const float*)d_in[8];
    const float* ln_g = (const float*)d_in[9];
    const float* ln_b = (const float*)d_in[10];
    float* out = (float*)d_out;

    float *qp, *kp, *vp, *cp, *yp;
    cudaGetSymbolAddress((void**)&qp, g_q);
    cudaGetSymbolAddress((void**)&kp, g_k);
    cudaGetSymbolAddress((void**)&vp, g_v);
    cudaGetSymbolAddress((void**)&cp, g_ctx);
    cudaGetSymbolAddress((void**)&yp, g_y);

    dim3 ggrid(Hdim / 64, Mtot / 64);
    gemm_kernel<<<ggrid, 256>>>(x, Wq, bq, nullptr, qp, 1);
    gemm_kernel<<<ggrid, 256>>>(x, Wk, bk, nullptr, kp, 1);
    gemm_kernel<<<ggrid, 256>>>(x, Wv, bv, nullptr, vp, 1);

    attn_kernel<<<dim3(Slen / 64, NHn, Bsz), 64>>>(qp, kp, vp, cp);

    gemm_kernel<<<ggrid, 256>>>(cp, Wo, bo, x, yp, 0);

    ln_kernel<<<Mtot, 256>>>(yp, ln_g, ln_b, out);
}

// round 2
// speedup vs baseline: 1.0531x; 1.0531x over previous
#include <cuda_runtime.h>
#include <math.h>

#define Bsz   2
#define Slen  2048
#define Hdim  1024
#define NHn   16
#define HDn   64
#define Mtot  (Bsz*Slen)   // 4096
#define EPSf  1e-12f

// -------- scratch (no allocations allowed) --------
__device__ float g_q[Mtot*Hdim];
__device__ float g_k[Mtot*Hdim];
__device__ float g_v[Mtot*Hdim];
__device__ float g_ctx[Mtot*Hdim];
__device__ float g_y[Mtot*Hdim];

// ============================================================
// C[M,N] = A[M,1024] @ W[N,1024]^T + bias, two epilogues:
//   headLayout=1 : scatter to [B,NH,S,HD] layout (QKV path)
//   headLayout=0 : out[m*H+n] = val + bias[n] + res[m*H+n] (O-proj + residual)
// Tiles: BM=BN=64, BK=16, 256 threads, 4x4 per thread.
// ============================================================
__global__ void gemm_kernel(const float* __restrict__ A, const float* __restrict__ W,
                            const float* __restrict__ bias, const float* __restrict__ res,
                            float* __restrict__ out, int headLayout)
{
    __shared__ float As[16][64];
    __shared__ float Bs[16][64];

    const int tid = threadIdx.x;               // 0..255
    const int n0  = blockIdx.x * 64;
    const int m0  = blockIdx.y * 64;
    const int tm  = (tid >> 4) * 4;            // 0..60
    const int tn  = (tid & 15) * 4;            // 0..60
    const int lr  = tid >> 2;                  // 0..63 (tile row to load)
    const int lk  = (tid & 3) * 4;             // 0,4,8,12

    float acc[4][4];
#pragma unroll
    for (int i = 0; i < 4; i++)
#pragma unroll
        for (int j = 0; j < 4; j++) acc[i][j] = 0.f;

    for (int k0 = 0; k0 < Hdim; k0 += 16) {
        float4 a4 = *(const float4*)(A + (size_t)(m0 + lr) * Hdim + k0 + lk);
        float4 b4 = *(const float4*)(W + (size_t)(n0 + lr) * Hdim + k0 + lk);
        As[lk + 0][lr] = a4.x; As[lk + 1][lr] = a4.y;
        As[lk + 2][lr] = a4.z; As[lk + 3][lr] = a4.w;
        Bs[lk + 0][lr] = b4.x; Bs[lk + 1][lr] = b4.y;
        Bs[lk + 2][lr] = b4.z; Bs[lk + 3][lr] = b4.w;
        __syncthreads();

#pragma unroll
        for (int kk = 0; kk < 16; kk++) {
            float4 ar = *(const float4*)&As[kk][tm];
            float4 br = *(const float4*)&Bs[kk][tn];
            float a[4] = {ar.x, ar.y, ar.z, ar.w};
            float b[4] = {br.x, br.y, br.z, br.w};
#pragma unroll
            for (int i = 0; i < 4; i++)
#pragma unroll
                for (int j = 0; j < 4; j++) acc[i][j] += a[i] * b[j];
        }
        __syncthreads();
    }

    if (headLayout) {
#pragma unroll
        for (int i = 0; i < 4; i++) {
            const int m = m0 + tm + i;
            const int b = m >> 11;         // /Slen
            const int s = m & (Slen - 1);
#pragma unroll
            for (int j = 0; j < 4; j++) {
                const int n = n0 + tn + j;
                const int h = n >> 6;
                const int d = n & 63;
                out[(((size_t)(b * NHn + h) * Slen) + s) * HDn + d] = acc[i][j] + bias[n];
            }
        }
    } else {
#pragma unroll
        for (int i = 0; i < 4; i++) {
            const int m = m0 + tm + i;
#pragma unroll
            for (int j = 0; j < 4; j++) {
                const int n = n0 + tn + j;
                out[(size_t)m * Hdim + n] = acc[i][j] + bias[n] + res[(size_t)m * Hdim + n];
            }
        }
    }
}

// ============================================================
// Causal flash attention, fp32. Q/K/V in [B,NH,S,HD] layout.
// Block = 64 threads = 64 query rows; K/V tiles of 64 keys in smem.
// Q tile transposed+XOR-swizzled in smem -> conflict-free per-thread column.
// ctx written back in [B,S,H] layout for the O-proj GEMM.
// ============================================================
__global__ void attn_kernel(const float* __restrict__ Q, const float* __restrict__ K,
                            const float* __restrict__ V, float* __restrict__ ctx)
{
    __shared__ float qs[64 * 64];
    __shared__ float ks[64 * 64];
    __shared__ float vs[64 * 64];

    const int t  = threadIdx.x;          // 0..63
    const int qt = blockIdx.x;           // query tile
    const int h  = blockIdx.y;
    const int b  = blockIdx.z;
    const int m0 = qt * 64;
    const int m  = m0 + t;               // this thread's query row

    const size_t base = (size_t)(b * NHn + h) * Slen * HDn;
    const float* Qb = Q + base;
    const float* Kb = K + base;
    const float* Vb = V + base;

    // load Q tile transposed: element (d=t, row=i) at slot t*64 + (i ^ (t&31))
    for (int i = 0; i < 64; i++)
        qs[t * 64 + (i ^ (t & 31))] = Qb[(size_t)(m0 + i) * HDn + t];

    float acc[64];
#pragma unroll
    for (int d = 0; d < 64; d++) acc[d] = 0.f;
    float m_i = -1e30f, l = 0.f;
    float sc[64];

    for (int kt = 0; kt <= qt; kt++) {
        const int k0 = kt * 64;
        __syncthreads();
        for (int i = 0; i < 64; i++) {
            ks[i * 64 + t] = Kb[(size_t)(k0 + i) * HDn + t];
            vs[i * 64 + t] = Vb[(size_t)(k0 + i) * HDn + t];
        }
        __syncthreads();

        // scores
#pragma unroll 1
        for (int kk = 0; kk < 64; kk++) {
            float s = 0.f;
#pragma unroll
            for (int d = 0; d < 64; d++)
                s += qs[d * 64 + (t ^ (d & 31))] * ks[kk * 64 + d];
            sc[kk] = (k0 + kk <= m) ? s * 0.125f : -1e30f;
        }

        // online softmax
        float mx = m_i;
#pragma unroll 1
        for (int kk = 0; kk < 64; kk++) mx = fmaxf(mx, sc[kk]);
        const float corr = __expf(m_i - mx);
        l *= corr;
#pragma unroll
        for (int d = 0; d < 64; d++) acc[d] *= corr;
#pragma unroll 1
        for (int kk = 0; kk < 64; kk++) {
            const float p = __expf(sc[kk] - mx);
            l += p;
#pragma unroll
            for (int d = 0; d < 64; d++) acc[d] += p * vs[kk * 64 + d];
        }
        m_i = mx;
    }

    const float inv = 1.f / l;
    float* outp = ctx + ((size_t)(b * Slen + m)) * Hdim + h * HDn;
#pragma unroll
    for (int d = 0; d < 64; d++) outp[d] = acc[d] * inv;
}

// ============================================================
// Row LayerNorm over H=1024; one block (256 thr, float4) per row.
// ============================================================
__global__ void ln_kernel(const float* __restrict__ y, const float* __restrict__ g,
                          const float* __restrict__ be, float* __restrict__ out)
{
    __shared__ float red[256];
    const int row = blockIdx.x;
    const int tid = threadIdx.x;
    const float4 v = ((const float4*)(y + (size_t)row * Hdim))[tid];

    float sum = v.x + v.y + v.z + v.w;
    red[tid] = sum; __syncthreads();
    for (int s = 128; s > 0; s >>= 1) {
        if (tid < s) red[tid] += red[tid + s];
        __syncthreads();
    }
    const float mu = red[0] * (1.f / 1024.f);
    __syncthreads();

    const float d0 = v.x - mu, d1 = v.y - mu, d2 = v.z - mu, d3 = v.w - mu;
    red[tid] = d0 * d0 + d1 * d1 + d2 * d2 + d3 * d3; __syncthreads();
    for (int s = 128; s > 0; s >>= 1) {
        if (tid < s) red[tid] += red[tid + s];
        __syncthreads();
    }
    const float inv = rsqrtf(red[0] * (1.f / 1024.f) + EPSf);

    const float4 gg = ((const float4*)g)[tid];
    const float4 bb = ((const float4*)be)[tid];
    float4 o;
    o.x = d0 * inv * gg.x + bb.x;
    o.y = d1 * inv * gg.y + bb.y;
    o.z = d2 * inv * gg.z + bb.z;
    o.w = d3 * inv * gg.w + bb.w;
    ((float4*)(out + (size_t)row * Hdim))[tid] = o;
}

// ============================================================
extern "C" void kernel_launch(void* const* d_in, const int* in_sizes, int n_in,
                              void* d_out, int out_size)
{
    const float* x    = (const float*)d_in[0];
    const float* Wq   = (const float*)d_in[1];
    const float* bq   = (const float*)d_in[2];
    const float* Wk   = (const float*)d_in[3];
    const float* bk   = (const float*)d_in[4];
    const float* Wv   = (const float*)d_in[5];
    const float* bv   = (const float*)d_in[6];
    const float* Wo   = (const float*)d_in[7];
    const float* bo   = (const float*)d_in[8];
    const float* ln_g = (const float*)d_in[9];
    const float* ln_b = (const float*)d_in[10];
    float* out = (float*)d_out;

    float *qp, *kp, *vp, *cp, *yp;
    cudaGetSymbolAddress((void**)&qp, g_q);
    cudaGetSymbolAddress((void**)&kp, g_k);
    cudaGetSymbolAddress((void**)&vp, g_v);
    cudaGetSymbolAddress((void**)&cp, g_ctx);
    cudaGetSymbolAddress((void**)&yp, g_y);

    dim3 ggrid(Hdim / 64, Mtot / 64);
    gemm_kernel<<<ggrid, 256>>>(x, Wq, bq, nullptr, qp, 1);
    gemm_kernel<<<ggrid, 256>>>(x, Wk, bk, nullptr, kp, 1);
    gemm_kernel<<<ggrid, 256>>>(x, Wv, bv, nullptr, vp, 1);

    attn_kernel<<<dim3(Slen / 64, NHn, Bsz), 64>>>(qp, kp, vp, cp);

    gemm_kernel<<<ggrid, 256>>>(cp, Wo, bo, x, yp, 0);

    ln_kernel<<<Mtot, 256>>>(yp, ln_g, ln_b, out);
}

// round 6
// speedup vs baseline: 1.4476x; 1.3745x over previous
#include <cuda_runtime.h>
#include <cuda_bf16.h>
#include <stdint.h>
#include <math.h>

#define Bsz   2
#define Slen  2048
#define Hdim  1024
#define NHn   16
#define HDn   64
#define Mtot  (Bsz*Slen)
#define EPSf  1e-12f

// -------- scratch (no allocations allowed) --------
__device__ float g_q[Mtot*Hdim];
__device__ float g_k[Mtot*Hdim];
__device__ float g_v[Mtot*Hdim];
__device__ float g_ctx[Mtot*Hdim];
__device__ float g_y[Mtot*Hdim];
__device__ __nv_bfloat16 g_xhi[Mtot*Hdim], g_xlo[Mtot*Hdim];
__device__ __nv_bfloat16 g_whi[4*Hdim*Hdim], g_wlo[4*Hdim*Hdim];
__device__ __nv_bfloat16 g_chi[Mtot*Hdim], g_clo[Mtot*Hdim];

// ---------------- helpers ----------------
__device__ __forceinline__ uint32_t smem_u32(const void* p) {
    uint32_t a;
    asm("{ .reg .u64 t; cvta.to.shared.u64 t, %1; cvt.u32.u64 %0, t; }" : "=r"(a) : "l"(p));
    return a;
}
#define LDSM_X4(r0,r1,r2,r3,addr) \
    asm volatile("ldmatrix.sync.aligned.m8n8.x4.shared.b16 {%0,%1,%2,%3}, [%4];" \
        : "=r"(r0),"=r"(r1),"=r"(r2),"=r"(r3) : "r"(addr))
#define MMA16816(c, a, b) \
    asm volatile("mma.sync.aligned.m16n8k16.row.col.f32.bf16.bf16.f32 " \
        "{%0,%1,%2,%3}, {%4,%5,%6,%7}, {%8,%9}, {%0,%1,%2,%3};" \
        : "+f"((c)[0]),"+f"((c)[1]),"+f"((c)[2]),"+f"((c)[3]) \
        : "r"((a)[0]),"r"((a)[1]),"r"((a)[2]),"r"((a)[3]), "r"((b)[0]),"r"((b)[1]))

// ---------------- split fp32 -> bf16 hi/lo ----------------
__global__ void split_kernel(const float* __restrict__ src, __nv_bfloat16* __restrict__ hi,
                             __nv_bfloat16* __restrict__ lo) {
    int i = blockIdx.x * 256 + threadIdx.x;
    float x = src[i];
    __nv_bfloat16 h = __float2bfloat16(x);
    hi[i] = h;
    lo[i] = __float2bfloat16(x - __bfloat162float(h));
}

// ---------------- bf16x3 GEMM via mma.sync: C = A @ W^T (+bias [+res]) ----------------
// CTA 128x128, BK=32, 8 warps of 64x32. Padded smem LDA=40 (conflict-free ldmatrix).
#define LDA 40
__global__ void __launch_bounds__(256) gemm_mma(
    const __nv_bfloat16* __restrict__ Ah, const __nv_bfloat16* __restrict__ Al,
    const __nv_bfloat16* __restrict__ Wh, const __nv_bfloat16* __restrict__ Wl,
    const float* __restrict__ bias, const float* __restrict__ res,
    float* __restrict__ out, int headLayout)
{
    __shared__ __align__(16) __nv_bfloat16 As_h[128*LDA];
    __shared__ __align__(16) __nv_bfloat16 As_l[128*LDA];
    __shared__ __align__(16) __nv_bfloat16 Bs_h[128*LDA];
    __shared__ __align__(16) __nv_bfloat16 Bs_l[128*LDA];

    const int tid = threadIdx.x, wid = tid >> 5, lane = tid & 31;
    const int n0 = blockIdx.x * 128, m0 = blockIdx.y * 128;
    const int wm0 = (wid & 1) * 64, wn0 = (wid >> 1) * 32;

    float acc[4][4][4];
#pragma unroll
    for (int i = 0; i < 4; i++)
#pragma unroll
        for (int j = 0; j < 4; j++)
#pragma unroll
            for (int v = 0; v < 4; v++) acc[i][j][v] = 0.f;

    // ldmatrix source addresses
    const uint32_t a_h_base = smem_u32(As_h);
    const uint32_t a_l_base = smem_u32(As_l);
    const uint32_t b_h_base = smem_u32(Bs_h);
    const uint32_t b_l_base = smem_u32(Bs_l);
    const int a_row = wm0 + (lane & 15);                     // + mf*16
    const int b_row = wn0 + (lane & 7) + ((lane >> 4) * 8);  // + nfp*16
    const int a_coff = (lane >> 4) * 8;                      // + kk
    const int b_coff = ((lane >> 3) & 1) * 8;                // + kk

    for (int k0 = 0; k0 < Hdim; k0 += 32) {
        // load full 128x32 tile: 512 uint4s, 2 per thread
#pragma unroll
        for (int i = 0; i < 2; i++) {
            const int u = i * 256 + tid;
            const int r = u >> 2;           // 0..127
            const int c = (u & 3) * 8;      // 0,8,16,24
            const size_t ga = (size_t)(m0 + r) * Hdim + k0 + c;
            const size_t gb = (size_t)(n0 + r) * Hdim + k0 + c;
            *(uint4*)&As_h[r * LDA + c] = *(const uint4*)(Ah + ga);
            *(uint4*)&As_l[r * LDA + c] = *(const uint4*)(Al + ga);
            *(uint4*)&Bs_h[r * LDA + c] = *(const uint4*)(Wh + gb);
            *(uint4*)&Bs_l[r * LDA + c] = *(const uint4*)(Wl + gb);
        }
        __syncthreads();

#pragma unroll
        for (int kf = 0; kf < 2; kf++) {
            const int kk = kf * 16;
            uint32_t ah[4][4], al[4][4];
#pragma unroll
            for (int mf = 0; mf < 4; mf++) {
                const uint32_t off = (uint32_t)(((a_row + mf * 16) * LDA + kk + a_coff) * 2);
                LDSM_X4(ah[mf][0], ah[mf][1], ah[mf][2], ah[mf][3], a_h_base + off);
                LDSM_X4(al[mf][0], al[mf][1], al[mf][2], al[mf][3], a_l_base + off);
            }
#pragma unroll
            for (int nfp = 0; nfp < 2; nfp++) {
                const uint32_t off = (uint32_t)(((b_row + nfp * 16) * LDA + kk + b_coff) * 2);
                uint32_t bh[4], bl[4];
                LDSM_X4(bh[0], bh[1], bh[2], bh[3], b_h_base + off);
                LDSM_X4(bl[0], bl[1], bl[2], bl[3], b_l_base + off);
#pragma unroll
                for (int mf = 0; mf < 4; mf++) {
#pragma unroll
                    for (int hf = 0; hf < 2; hf++) {
                        float* c = acc[mf][nfp * 2 + hf];
                        MMA16816(c, ah[mf], bh + hf * 2);
                        MMA16816(c, ah[mf], bl + hf * 2);
                        MMA16816(c, al[mf], bh + hf * 2);
                    }
                }
            }
        }
        __syncthreads();
    }

    // ---------------- epilogue ----------------
    const int rbase = m0 + wm0 + (lane >> 2);
    const int cbase = n0 + wn0 + (lane & 3) * 2;
#pragma unroll
    for (int mf = 0; mf < 4; mf++) {
#pragma unroll
        for (int nf = 0; nf < 4; nf++) {
#pragma unroll
            for (int half = 0; half < 2; half++) {
                const int r = rbase + mf * 16 + half * 8;
                const int c = cbase + nf * 8;
                float2 o;
                o.x = acc[mf][nf][half * 2 + 0] + bias[c];
                o.y = acc[mf][nf][half * 2 + 1] + bias[c + 1];
                if (headLayout) {
                    const int b = r >> 11, s = r & (Slen - 1);
                    const int h = c >> 6, d = c & 63;
                    *(float2*)(out + (((size_t)(b * NHn + h) * Slen) + s) * HDn + d) = o;
                } else {
                    const size_t idx = (size_t)r * Hdim + c;
                    float2 rv = *(const float2*)(res + idx);
                    o.x += rv.x; o.y += rv.y;
                    *(float2*)(out + idx) = o;
                }
            }
        }
    }
}

// ---------------- causal flash attention (fp32, unchanged) ----------------
__global__ void attn_kernel(const float* __restrict__ Q, const float* __restrict__ K,
                            const float* __restrict__ V, float* __restrict__ ctx)
{
    __shared__ float qs[64 * 64];
    __shared__ float ks[64 * 64];
    __shared__ float vs[64 * 64];
    const int t = threadIdx.x;
    const int qt = blockIdx.x, h = blockIdx.y, b = blockIdx.z;
    const int m0 = qt * 64, m = m0 + t;
    const size_t base = (size_t)(b * NHn + h) * Slen * HDn;
    const float* Qb = Q + base;
    const float* Kb = K + base;
    const float* Vb = V + base;

    for (int i = 0; i < 64; i++)
        qs[t * 64 + (i ^ (t & 31))] = Qb[(size_t)(m0 + i) * HDn + t];

    float acc[64];
#pragma unroll
    for (int d = 0; d < 64; d++) acc[d] = 0.f;
    float m_i = -1e30f, l = 0.f;
    float sc[64];

    for (int kt = 0; kt <= qt; kt++) {
        const int k0 = kt * 64;
        __syncthreads();
        for (int i = 0; i < 64; i++) {
            ks[i * 64 + t] = Kb[(size_t)(k0 + i) * HDn + t];
            vs[i * 64 + t] = Vb[(size_t)(k0 + i) * HDn + t];
        }
        __syncthreads();
#pragma unroll 1
        for (int kk = 0; kk < 64; kk++) {
            float s = 0.f;
#pragma unroll
            for (int d = 0; d < 64; d++)
                s += qs[d * 64 + (t ^ (d & 31))] * ks[kk * 64 + d];
            sc[kk] = (k0 + kk <= m) ? s * 0.125f : -1e30f;
        }
        float mx = m_i;
#pragma unroll 1
        for (int kk = 0; kk < 64; kk++) mx = fmaxf(mx, sc[kk]);
        const float corr = __expf(m_i - mx);
        l *= corr;
#pragma unroll
        for (int d = 0; d < 64; d++) acc[d] *= corr;
#pragma unroll 1
        for (int kk = 0; kk < 64; kk++) {
            const float p = __expf(sc[kk] - mx);
            l += p;
#pragma unroll
            for (int d = 0; d < 64; d++) acc[d] += p * vs[kk * 64 + d];
        }
        m_i = mx;
    }
    const float inv = 1.f / l;
    float* outp = ctx + ((size_t)(b * Slen + m)) * Hdim + h * HDn;
#pragma unroll
    for (int d = 0; d < 64; d++) outp[d] = acc[d] * inv;
}

// ---------------- LayerNorm (unchanged) ----------------
__global__ void ln_kernel(const float* __restrict__ y, const float* __restrict__ g,
                          const float* __restrict__ be, float* __restrict__ out)
{
    __shared__ float red[256];
    const int row = blockIdx.x, tid = threadIdx.x;
    const float4 v = ((const float4*)(y + (size_t)row * Hdim))[tid];
    float sum = v.x + v.y + v.z + v.w;
    red[tid] = sum; __syncthreads();
    for (int s = 128; s > 0; s >>= 1) { if (tid < s) red[tid] += red[tid + s]; __syncthreads(); }
    const float mu = red[0] * (1.f / 1024.f);
    __syncthreads();
    const float d0 = v.x - mu, d1 = v.y - mu, d2 = v.z - mu, d3 = v.w - mu;
    red[tid] = d0 * d0 + d1 * d1 + d2 * d2 + d3 * d3; __syncthreads();
    for (int s = 128; s > 0; s >>= 1) { if (tid < s) red[tid] += red[tid + s]; __syncthreads(); }
    const float inv = rsqrtf(red[0] * (1.f / 1024.f) + EPSf);
    const float4 gg = ((const float4*)g)[tid];
    const float4 bb = ((const float4*)be)[tid];
    float4 o;
    o.x = d0 * inv * gg.x + bb.x;
    o.y = d1 * inv * gg.y + bb.y;
    o.z = d2 * inv * gg.z + bb.z;
    o.w = d3 * inv * gg.w + bb.w;
    ((float4*)(out + (size_t)row * Hdim))[tid] = o;
}

// ---------------- launch ----------------
extern "C" void kernel_launch(void* const* d_in, const int* in_sizes, int n_in,
                              void* d_out, int out_size)
{
    const float* x    = (const float*)d_in[0];
    const float* Wq   = (const float*)d_in[1];
    const float* bq   = (const float*)d_in[2];
    const float* Wk   = (const float*)d_in[3];
    const float* bk   = (const float*)d_in[4];
    const float* Wv   = (const float*)d_in[5];
    const float* bv   = (const float*)d_in[6];
    const float* Wo   = (const float*)d_in[7];
    const float* bo   = (const float*)d_in[8];
    const float* ln_g = (const float*)d_in[9];
    const float* ln_b = (const float*)d_in[10];
    float* out = (float*)d_out;

    float *qp, *kp, *vp, *cp, *yp;
    __nv_bfloat16 *xh, *xl, *wh, *wl, *ch, *cl;
    cudaGetSymbolAddress((void**)&qp, g_q);
    cudaGetSymbolAddress((void**)&kp, g_k);
    cudaGetSymbolAddress((void**)&vp, g_v);
    cudaGetSymbolAddress((void**)&cp, g_ctx);
    cudaGetSymbolAddress((void**)&yp, g_y);
    cudaGetSymbolAddress((void**)&xh, g_xhi);
    cudaGetSymbolAddress((void**)&xl, g_xlo);
    cudaGetSymbolAddress((void**)&wh, g_whi);
    cudaGetSymbolAddress((void**)&wl, g_wlo);
    cudaGetSymbolAddress((void**)&ch, g_chi);
    cudaGetSymbolAddress((void**)&cl, g_clo);

    const int WSZ = Hdim * Hdim;
    split_kernel<<<Mtot * Hdim / 256, 256>>>(x, xh, xl);
    split_kernel<<<WSZ / 256, 256>>>(Wq, wh + 0 * WSZ, wl + 0 * WSZ);
    split_kernel<<<WSZ / 256, 256>>>(Wk, wh + 1 * WSZ, wl + 1 * WSZ);
    split_kernel<<<WSZ / 256, 256>>>(Wv, wh + 2 * WSZ, wl + 2 * WSZ);
    split_kernel<<<WSZ / 256, 256>>>(Wo, wh + 3 * WSZ, wl + 3 * WSZ);

    dim3 ggrid(Hdim / 128, Mtot / 128);
    gemm_mma<<<ggrid, 256>>>(xh, xl, wh + 0 * WSZ, wl + 0 * WSZ, bq, nullptr, qp, 1);
    gemm_mma<<<ggrid, 256>>>(xh, xl, wh + 1 * WSZ, wl + 1 * WSZ, bk, nullptr, kp, 1);
    gemm_mma<<<ggrid, 256>>>(xh, xl, wh + 2 * WSZ, wl + 2 * WSZ, bv, nullptr, vp, 1);

    attn_kernel<<<dim3(Slen / 64, NHn, Bsz), 64>>>(qp, kp, vp, cp);

    split_kernel<<<Mtot * Hdim / 256, 256>>>(cp, ch, cl);
    gemm_mma<<<ggrid, 256>>>(ch, cl, wh + 3 * WSZ, wl + 3 * WSZ, bo, x, yp, 0);

    ln_kernel<<<Mtot, 256>>>(yp, ln_g, ln_b, out);
}

// round 7
// speedup vs baseline: 4.3263x; 2.9886x over previous
#include <cuda_runtime.h>
#include <cuda_bf16.h>
#include <stdint.h>
#include <math.h>

#define Bsz   2
#define Slen  2048
#define Hdim  1024
#define NHn   16
#define HDn   64
#define Mtot  (Bsz*Slen)
#define EPSf  1e-12f

// -------- scratch (no allocations allowed) --------
__device__ float g_y[Mtot*Hdim];
__device__ __nv_bfloat16 g_xhi[Mtot*Hdim], g_xlo[Mtot*Hdim];
__device__ __nv_bfloat16 g_whi[4*Hdim*Hdim], g_wlo[4*Hdim*Hdim];
__device__ __nv_bfloat16 g_qh[Mtot*Hdim], g_ql[Mtot*Hdim];
__device__ __nv_bfloat16 g_kh[Mtot*Hdim], g_kl[Mtot*Hdim];
__device__ __nv_bfloat16 g_vh[Mtot*Hdim], g_vl[Mtot*Hdim];
__device__ __nv_bfloat16 g_ch[Mtot*Hdim], g_cl[Mtot*Hdim];

// ---------------- helpers ----------------
__device__ __forceinline__ uint32_t smem_u32(const void* p) {
    uint32_t a;
    asm("{ .reg .u64 t; cvta.to.shared.u64 t, %1; cvt.u32.u64 %0, t; }" : "=r"(a) : "l"(p));
    return a;
}
#define LDSM_X4(r0,r1,r2,r3,addr) \
    asm volatile("ldmatrix.sync.aligned.m8n8.x4.shared.b16 {%0,%1,%2,%3}, [%4];" \
        : "=r"(r0),"=r"(r1),"=r"(r2),"=r"(r3) : "r"(addr))
#define LDSM_X4_T(r0,r1,r2,r3,addr) \
    asm volatile("ldmatrix.sync.aligned.m8n8.x4.trans.shared.b16 {%0,%1,%2,%3}, [%4];" \
        : "=r"(r0),"=r"(r1),"=r"(r2),"=r"(r3) : "r"(addr))
#define MMA16816(c, a, b) \
    asm volatile("mma.sync.aligned.m16n8k16.row.col.f32.bf16.bf16.f32 " \
        "{%0,%1,%2,%3}, {%4,%5,%6,%7}, {%8,%9}, {%0,%1,%2,%3};" \
        : "+f"((c)[0]),"+f"((c)[1]),"+f"((c)[2]),"+f"((c)[3]) \
        : "r"((a)[0]),"r"((a)[1]),"r"((a)[2]),"r"((a)[3]), "r"((b)[0]),"r"((b)[1]))

__device__ __forceinline__ uint32_t pk_bf16x2(float lo, float hi) {
    uint32_t r;
    asm("cvt.rn.bf16x2.f32 %0, %1, %2;" : "=r"(r) : "f"(hi), "f"(lo));
    return r;
}

// ---------------- split fp32 -> bf16 hi/lo ----------------
__global__ void split_kernel(const float* __restrict__ src, __nv_bfloat16* __restrict__ hi,
                             __nv_bfloat16* __restrict__ lo) {
    int i = blockIdx.x * 256 + threadIdx.x;
    float x = src[i];
    __nv_bfloat16 h = __float2bfloat16(x);
    hi[i] = h;
    lo[i] = __float2bfloat16(x - __bfloat162float(h));
}

// ---------------- bf16x3 GEMM via mma.sync: C = A @ W^T (+bias [+res]) ----------------
// CTA 128x128, BK=32, 8 warps of 64x32. Padded smem LDA=40 (conflict-free ldmatrix).
// headLayout=1: write bf16 hi/lo pair buffers in [B,NH,S,HD] layout.
// headLayout=0: write fp32 out + bias + residual.
#define LDA 40
__global__ void __launch_bounds__(256) gemm_mma(
    const __nv_bfloat16* __restrict__ Ah, const __nv_bfloat16* __restrict__ Al,
    const __nv_bfloat16* __restrict__ Wh, const __nv_bfloat16* __restrict__ Wl,
    const float* __restrict__ bias, const float* __restrict__ res,
    float* __restrict__ out, __nv_bfloat16* __restrict__ outH, __nv_bfloat16* __restrict__ outL,
    int headLayout)
{
    __shared__ __align__(16) __nv_bfloat16 As_h[128*LDA];
    __shared__ __align__(16) __nv_bfloat16 As_l[128*LDA];
    __shared__ __align__(16) __nv_bfloat16 Bs_h[128*LDA];
    __shared__ __align__(16) __nv_bfloat16 Bs_l[128*LDA];

    const int tid = threadIdx.x, wid = tid >> 5, lane = tid & 31;
    const int n0 = blockIdx.x * 128, m0 = blockIdx.y * 128;
    const int wm0 = (wid & 1) * 64, wn0 = (wid >> 1) * 32;

    float acc[4][4][4];
#pragma unroll
    for (int i = 0; i < 4; i++)
#pragma unroll
        for (int j = 0; j < 4; j++)
#pragma unroll
            for (int v = 0; v < 4; v++) acc[i][j][v] = 0.f;

    const uint32_t a_h_base = smem_u32(As_h);
    const uint32_t a_l_base = smem_u32(As_l);
    const uint32_t b_h_base = smem_u32(Bs_h);
    const uint32_t b_l_base = smem_u32(Bs_l);
    const int a_row = wm0 + (lane & 15);
    const int b_row = wn0 + (lane & 7) + ((lane >> 4) * 8);
    const int a_coff = (lane >> 4) * 8;
    const int b_coff = ((lane >> 3) & 1) * 8;

    for (int k0 = 0; k0 < Hdim; k0 += 32) {
#pragma unroll
        for (int i = 0; i < 2; i++) {
            const int u = i * 256 + tid;
            const int r = u >> 2;
            const int c = (u & 3) * 8;
            const size_t ga = (size_t)(m0 + r) * Hdim + k0 + c;
            const size_t gb = (size_t)(n0 + r) * Hdim + k0 + c;
            *(uint4*)&As_h[r * LDA + c] = *(const uint4*)(Ah + ga);
            *(uint4*)&As_l[r * LDA + c] = *(const uint4*)(Al + ga);
            *(uint4*)&Bs_h[r * LDA + c] = *(const uint4*)(Wh + gb);
            *(uint4*)&Bs_l[r * LDA + c] = *(const uint4*)(Wl + gb);
        }
        __syncthreads();

#pragma unroll
        for (int kf = 0; kf < 2; kf++) {
            const int kk = kf * 16;
            uint32_t ah[4][4], al[4][4];
#pragma unroll
            for (int mf = 0; mf < 4; mf++) {
                const uint32_t off = (uint32_t)(((a_row + mf * 16) * LDA + kk + a_coff) * 2);
                LDSM_X4(ah[mf][0], ah[mf][1], ah[mf][2], ah[mf][3], a_h_base + off);
                LDSM_X4(al[mf][0], al[mf][1], al[mf][2], al[mf][3], a_l_base + off);
            }
#pragma unroll
            for (int nfp = 0; nfp < 2; nfp++) {
                const uint32_t off = (uint32_t)(((b_row + nfp * 16) * LDA + kk + b_coff) * 2);
                uint32_t bh[4], bl[4];
                LDSM_X4(bh[0], bh[1], bh[2], bh[3], b_h_base + off);
                LDSM_X4(bl[0], bl[1], bl[2], bl[3], b_l_base + off);
#pragma unroll
                for (int mf = 0; mf < 4; mf++) {
#pragma unroll
                    for (int hf = 0; hf < 2; hf++) {
                        float* c = acc[mf][nfp * 2 + hf];
                        MMA16816(c, ah[mf], bh + hf * 2);
                        MMA16816(c, ah[mf], bl + hf * 2);
                        MMA16816(c, al[mf], bh + hf * 2);
                    }
                }
            }
        }
        __syncthreads();
    }

    const int rbase = m0 + wm0 + (lane >> 2);
    const int cbase = n0 + wn0 + (lane & 3) * 2;
#pragma unroll
    for (int mf = 0; mf < 4; mf++) {
#pragma unroll
        for (int nf = 0; nf < 4; nf++) {
#pragma unroll
            for (int half = 0; half < 2; half++) {
                const int r = rbase + mf * 16 + half * 8;
                const int c = cbase + nf * 8;
                float v0 = acc[mf][nf][half * 2 + 0] + bias[c];
                float v1 = acc[mf][nf][half * 2 + 1] + bias[c + 1];
                if (headLayout) {
                    const int b = r >> 11, s = r & (Slen - 1);
                    const int h = c >> 6, d = c & 63;
                    const size_t idx = (((size_t)(b * NHn + h) * Slen) + s) * HDn + d;
                    __nv_bfloat16 h0 = __float2bfloat16(v0);
                    __nv_bfloat16 h1 = __float2bfloat16(v1);
                    float l0 = v0 - __bfloat162float(h0);
                    float l1 = v1 - __bfloat162float(h1);
                    *(uint32_t*)(outH + idx) =
                        ((uint32_t)__bfloat16_as_ushort(h1) << 16) | __bfloat16_as_ushort(h0);
                    *(uint32_t*)(outL + idx) = pk_bf16x2(l0, l1);
                } else {
                    const size_t idx = (size_t)r * Hdim + c;
                    float2 rv = *(const float2*)(res + idx);
                    float2 o;
                    o.x = v0 + rv.x; o.y = v1 + rv.y;
                    *(float2*)(out + idx) = o;
                }
            }
        }
    }
}

// ---------------- MMA flash attention (bf16x3), causal ----------------
// CTA: 64 queries, 4 warps (16 q-rows each). K/V tiles 64 keys in swizzled smem.
#define ALD 72
__global__ void __launch_bounds__(128) attn_mma(
    const __nv_bfloat16* __restrict__ Qh, const __nv_bfloat16* __restrict__ Ql,
    const __nv_bfloat16* __restrict__ Kh, const __nv_bfloat16* __restrict__ Kl,
    const __nv_bfloat16* __restrict__ Vh, const __nv_bfloat16* __restrict__ Vl,
    __nv_bfloat16* __restrict__ Ch, __nv_bfloat16* __restrict__ Cl)
{
    __shared__ __align__(16) __nv_bfloat16 sKh[64*ALD], sKl[64*ALD];
    __shared__ __align__(16) __nv_bfloat16 sVh[64*ALD], sVl[64*ALD];

    const int tid = threadIdx.x, wid = tid >> 5, lane = tid & 31;
    const int qt = blockIdx.x, h = blockIdx.y, b = blockIdx.z;
    const int m0 = qt * 64, wq0 = wid * 16;
    const size_t base = (size_t)(b * NHn + h) * Slen * HDn;

    const uint32_t aKh = smem_u32(sKh), aKl = smem_u32(sKl);
    const uint32_t aVh = smem_u32(sVh), aVl = smem_u32(sVl);

    // ---- stage Q hi/lo into sKh/sKl (reused before K loop) ----
    {
        const __nv_bfloat16* srcH = Qh + base + (size_t)m0 * HDn;
        const __nv_bfloat16* srcL = Ql + base + (size_t)m0 * HDn;
#pragma unroll
        for (int i = 0; i < 4; i++) {
            int u = i * 128 + tid, r = u >> 3, c = u & 7;
            int cs = c ^ ((r & 3) << 1);
            *(uint4*)&sKh[r * ALD + cs * 8] = *(const uint4*)(srcH + r * 64 + c * 8);
            *(uint4*)&sKl[r * ALD + cs * 8] = *(const uint4*)(srcL + r * 64 + c * 8);
        }
    }
    __syncthreads();

    // per-lane ldmatrix row/col patterns
    const int rA = (lane & 7) + ((lane >> 3) & 1) * 8;   // Q (x4) and V (x4.trans) row offset
    const int cA = (lane >> 4) & 1;
    const int rB = (lane & 7) + ((lane >> 4) << 3);      // K (x4) row offset
    const int cB = (lane >> 3) & 1;
    const int swzA = (rA & 3) << 1;
    const int swzB = (rB & 3) << 1;

    // ---- Q fragments ----
    uint32_t qfh[4][4], qfl[4][4];
    {
        const int row = wq0 + rA;
        const uint32_t rb = (uint32_t)(row * (ALD * 2));
        const int swz = (row & 3) << 1;
#pragma unroll
        for (int kb = 0; kb < 4; kb++) {
            const uint32_t off = rb + (uint32_t)(((2 * kb + cA) ^ swz) * 16);
            LDSM_X4(qfh[kb][0], qfh[kb][1], qfh[kb][2], qfh[kb][3], aKh + off);
            LDSM_X4(qfl[kb][0], qfl[kb][1], qfl[kb][2], qfl[kb][3], aKl + off);
        }
    }
    __syncthreads();

    float o[8][4];
#pragma unroll
    for (int i = 0; i < 8; i++)
#pragma unroll
        for (int v = 0; v < 4; v++) o[i][v] = 0.f;
    float mr0 = -1e30f, mr1 = -1e30f, lr0 = 0.f, lr1 = 0.f;

    for (int kt = 0; kt <= qt; kt++) {
        const int k0 = kt * 64;
        // ---- stage K/V hi/lo ----
        {
            const __nv_bfloat16* sK0 = Kh + base + (size_t)k0 * HDn;
            const __nv_bfloat16* sK1 = Kl + base + (size_t)k0 * HDn;
            const __nv_bfloat16* sV0 = Vh + base + (size_t)k0 * HDn;
            const __nv_bfloat16* sV1 = Vl + base + (size_t)k0 * HDn;
#pragma unroll
            for (int i = 0; i < 4; i++) {
                int u = i * 128 + tid, r = u >> 3, c = u & 7;
                int cs = c ^ ((r & 3) << 1);
                int so = r * ALD + cs * 8, go = r * 64 + c * 8;
                *(uint4*)&sKh[so] = *(const uint4*)(sK0 + go);
                *(uint4*)&sKl[so] = *(const uint4*)(sK1 + go);
                *(uint4*)&sVh[so] = *(const uint4*)(sV0 + go);
                *(uint4*)&sVl[so] = *(const uint4*)(sV1 + go);
            }
        }
        __syncthreads();

        // ---- S = Q K^T (bf16x3) ----
        float s[8][4];
#pragma unroll
        for (int i = 0; i < 8; i++)
#pragma unroll
            for (int v = 0; v < 4; v++) s[i][v] = 0.f;
#pragma unroll
        for (int kb = 0; kb < 4; kb++) {
#pragma unroll
            for (int np = 0; np < 4; np++) {
                const int row = np * 16 + rB;
                const uint32_t off = (uint32_t)(row * (ALD * 2) + (((2 * kb + cB) ^ swzB)) * 16);
                uint32_t kh[4], kl[4];
                LDSM_X4(kh[0], kh[1], kh[2], kh[3], aKh + off);
                LDSM_X4(kl[0], kl[1], kl[2], kl[3], aKl + off);
                MMA16816(s[2*np],   qfh[kb], kh);     MMA16816(s[2*np],   qfh[kb], kl);
                MMA16816(s[2*np],   qfl[kb], kh);
                MMA16816(s[2*np+1], qfh[kb], kh + 2); MMA16816(s[2*np+1], qfh[kb], kl + 2);
                MMA16816(s[2*np+1], qfl[kb], kh + 2);
            }
        }

        // ---- scale + causal mask ----
#pragma unroll
        for (int nf = 0; nf < 8; nf++)
#pragma unroll
            for (int v = 0; v < 4; v++) s[nf][v] *= 0.125f;
        if (kt == qt) {
            const int row0 = wq0 + (lane >> 2), row1 = row0 + 8;
            const int colb = (lane & 3) * 2;
#pragma unroll
            for (int nf = 0; nf < 8; nf++) {
                const int c0 = nf * 8 + colb, c1 = c0 + 1;
                if (c0 > row0) s[nf][0] = -1e30f;
                if (c1 > row0) s[nf][1] = -1e30f;
                if (c0 > row1) s[nf][2] = -1e30f;
                if (c1 > row1) s[nf][3] = -1e30f;
            }
        }

        // ---- online softmax ----
        float mx0 = s[0][0], mx1 = s[0][2];
#pragma unroll
        for (int nf = 0; nf < 8; nf++) {
            mx0 = fmaxf(mx0, fmaxf(s[nf][0], s[nf][1]));
            mx1 = fmaxf(mx1, fmaxf(s[nf][2], s[nf][3]));
        }
        mx0 = fmaxf(mx0, __shfl_xor_sync(0xffffffffu, mx0, 1));
        mx0 = fmaxf(mx0, __shfl_xor_sync(0xffffffffu, mx0, 2));
        mx1 = fmaxf(mx1, __shfl_xor_sync(0xffffffffu, mx1, 1));
        mx1 = fmaxf(mx1, __shfl_xor_sync(0xffffffffu, mx1, 2));
        const float nm0 = fmaxf(mr0, mx0), nm1 = fmaxf(mr1, mx1);
        const float cr0 = __expf(mr0 - nm0), cr1 = __expf(mr1 - nm1);
        lr0 *= cr0; lr1 *= cr1;
#pragma unroll
        for (int nf = 0; nf < 8; nf++) {
            o[nf][0] *= cr0; o[nf][1] *= cr0;
            o[nf][2] *= cr1; o[nf][3] *= cr1;
        }
        mr0 = nm0; mr1 = nm1;

        uint32_t ph[8], phb[8], pl[8], plb[8];
#pragma unroll
        for (int nf = 0; nf < 8; nf++) {
            float p0 = __expf(s[nf][0] - nm0), p1 = __expf(s[nf][1] - nm0);
            float p2 = __expf(s[nf][2] - nm1), p3 = __expf(s[nf][3] - nm1);
            lr0 += p0 + p1; lr1 += p2 + p3;
            ph[nf]  = pk_bf16x2(p0, p1);
            phb[nf] = pk_bf16x2(p2, p3);
            float h0 = __uint_as_float(ph[nf] << 16);
            float h1 = __uint_as_float(ph[nf] & 0xFFFF0000u);
            float h2 = __uint_as_float(phb[nf] << 16);
            float h3 = __uint_as_float(phb[nf] & 0xFFFF0000u);
            pl[nf]  = pk_bf16x2(p0 - h0, p1 - h1);
            plb[nf] = pk_bf16x2(p2 - h2, p3 - h3);
        }

        // ---- O += P V (bf16x3), P frags re-packed from S frags ----
#pragma unroll
        for (int kb = 0; kb < 4; kb++) {
            uint32_t pah[4] = { ph[2*kb], phb[2*kb], ph[2*kb+1], phb[2*kb+1] };
            uint32_t pal[4] = { pl[2*kb], plb[2*kb], pl[2*kb+1], plb[2*kb+1] };
            const int row = kb * 16 + rA;
            const uint32_t rb = (uint32_t)(row * (ALD * 2));
#pragma unroll
            for (int np = 0; np < 4; np++) {
                const uint32_t off = rb + (uint32_t)(((2 * np + cA) ^ swzA) * 16);
                uint32_t vh[4], vl[4];
                LDSM_X4_T(vh[0], vh[1], vh[2], vh[3], aVh + off);
                LDSM_X4_T(vl[0], vl[1], vl[2], vl[3], aVl + off);
                MMA16816(o[2*np],   pah, vh);     MMA16816(o[2*np],   pah, vl);
                MMA16816(o[2*np],   pal, vh);
                MMA16816(o[2*np+1], pah, vh + 2); MMA16816(o[2*np+1], pah, vl + 2);
                MMA16816(o[2*np+1], pal, vh + 2);
            }
        }
        __syncthreads();
    }

    // ---- finalize: l reduce, normalize, store ctx hi/lo in [B,S,H] ----
    lr0 += __shfl_xor_sync(0xffffffffu, lr0, 1);
    lr0 += __shfl_xor_sync(0xffffffffu, lr0, 2);
    lr1 += __shfl_xor_sync(0xffffffffu, lr1, 1);
    lr1 += __shfl_xor_sync(0xffffffffu, lr1, 2);
    const float iv0 = 1.f / lr0, iv1 = 1.f / lr1;

    const int s0 = m0 + wq0 + (lane >> 2), s1 = s0 + 8;
    const size_t rb0 = (size_t)(b * Slen + s0) * Hdim + h * 64;
    const size_t rb1 = (size_t)(b * Slen + s1) * Hdim + h * 64;
#pragma unroll
    for (int nf = 0; nf < 8; nf++) {
        const int col = nf * 8 + (lane & 3) * 2;
        float v0 = o[nf][0] * iv0, v1 = o[nf][1] * iv0;
        float v2 = o[nf][2] * iv1, v3 = o[nf][3] * iv1;
        __nv_bfloat16 h0 = __float2bfloat16(v0), h1 = __float2bfloat16(v1);
        __nv_bfloat16 h2 = __float2bfloat16(v2), h3 = __float2bfloat16(v3);
        *(uint32_t*)(Ch + rb0 + col) =
            ((uint32_t)__bfloat16_as_ushort(h1) << 16) | __bfloat16_as_ushort(h0);
        *(uint32_t*)(Ch + rb1 + col) =
            ((uint32_t)__bfloat16_as_ushort(h3) << 16) | __bfloat16_as_ushort(h2);
        *(uint32_t*)(Cl + rb0 + col) =
            pk_bf16x2(v0 - __bfloat162float(h0), v1 - __bfloat162float(h1));
        *(uint32_t*)(Cl + rb1 + col) =
            pk_bf16x2(v2 - __bfloat162float(h2), v3 - __bfloat162float(h3));
    }
}

// ---------------- LayerNorm ----------------
__global__ void ln_kernel(const float* __restrict__ y, const float* __restrict__ g,
                          const float* __restrict__ be, float* __restrict__ out)
{
    __shared__ float red[256];
    const int row = blockIdx.x, tid = threadIdx.x;
    const float4 v = ((const float4*)(y + (size_t)row * Hdim))[tid];
    float sum = v.x + v.y + v.z + v.w;
    red[tid] = sum; __syncthreads();
    for (int s = 128; s > 0; s >>= 1) { if (tid < s) red[tid] += red[tid + s]; __syncthreads(); }
    const float mu = red[0] * (1.f / 1024.f);
    __syncthreads();
    const float d0 = v.x - mu, d1 = v.y - mu, d2 = v.z - mu, d3 = v.w - mu;
    red[tid] = d0 * d0 + d1 * d1 + d2 * d2 + d3 * d3; __syncthreads();
    for (int s = 128; s > 0; s >>= 1) { if (tid < s) red[tid] += red[tid + s]; __syncthreads(); }
    const float inv = rsqrtf(red[0] * (1.f / 1024.f) + EPSf);
    const float4 gg = ((const float4*)g)[tid];
    const float4 bb = ((const float4*)be)[tid];
    float4 o;
    o.x = d0 * inv * gg.x + bb.x;
    o.y = d1 * inv * gg.y + bb.y;
    o.z = d2 * inv * gg.z + bb.z;
    o.w = d3 * inv * gg.w + bb.w;
    ((float4*)(out + (size_t)row * Hdim))[tid] = o;
}

// ---------------- launch ----------------
extern "C" void kernel_launch(void* const* d_in, const int* in_sizes, int n_in,
                              void* d_out, int out_size)
{
    const float* x    = (const float*)d_in[0];
    const float* Wq   = (const float*)d_in[1];
    const float* bq   = (const float*)d_in[2];
    const float* Wk   = (const float*)d_in[3];
    const float* bk   = (const float*)d_in[4];
    const float* Wv   = (const float*)d_in[5];
    const float* bv   = (const float*)d_in[6];
    const float* Wo   = (const float*)d_in[7];
    const float* bo   = (const float*)d_in[8];
    const float* ln_g = (const float*)d_in[9];
    const float* ln_b = (const float*)d_in[10];
    float* out = (float*)d_out;

    float *yp;
    __nv_bfloat16 *xh, *xl, *wh, *wl, *qh, *ql, *kh, *kl, *vh, *vl, *ch, *cl;
    cudaGetSymbolAddress((void**)&yp, g_y);
    cudaGetSymbolAddress((void**)&xh, g_xhi);
    cudaGetSymbolAddress((void**)&xl, g_xlo);
    cudaGetSymbolAddress((void**)&wh, g_whi);
    cudaGetSymbolAddress((void**)&wl, g_wlo);
    cudaGetSymbolAddress((void**)&qh, g_qh);
    cudaGetSymbolAddress((void**)&ql, g_ql);
    cudaGetSymbolAddress((void**)&kh, g_kh);
    cudaGetSymbolAddress((void**)&kl, g_kl);
    cudaGetSymbolAddress((void**)&vh, g_vh);
    cudaGetSymbolAddress((void**)&vl, g_vl);
    cudaGetSymbolAddress((void**)&ch, g_ch);
    cudaGetSymbolAddress((void**)&cl, g_cl);

    const int WSZ = Hdim * Hdim;
    split_kernel<<<Mtot * Hdim / 256, 256>>>(x, xh, xl);
    split_kernel<<<WSZ / 256, 256>>>(Wq, wh + 0 * WSZ, wl + 0 * WSZ);
    split_kernel<<<WSZ / 256, 256>>>(Wk, wh + 1 * WSZ, wl + 1 * WSZ);
    split_kernel<<<WSZ / 256, 256>>>(Wv, wh + 2 * WSZ, wl + 2 * WSZ);
    split_kernel<<<WSZ / 256, 256>>>(Wo, wh + 3 * WSZ, wl + 3 * WSZ);

    dim3 ggrid(Hdim / 128, Mtot / 128);
    gemm_mma<<<ggrid, 256>>>(xh, xl, wh + 0 * WSZ, wl + 0 * WSZ, bq, nullptr, nullptr, qh, ql, 1);
    gemm_mma<<<ggrid, 256>>>(xh, xl, wh + 1 * WSZ, wl + 1 * WSZ, bk, nullptr, nullptr, kh, kl, 1);
    gemm_mma<<<ggrid, 256>>>(xh, xl, wh + 2 * WSZ, wl + 2 * WSZ, bv, nullptr, nullptr, vh, vl, 1);

    attn_mma<<<dim3(Slen / 64, NHn, Bsz), 128>>>(qh, ql, kh, kl, vh, vl, ch, cl);

    gemm_mma<<<ggrid, 256>>>(ch, cl, wh + 3 * WSZ, wl + 3 * WSZ, bo, x, yp, nullptr, nullptr, 0);

    ln_kernel<<<Mtot, 256>>>(yp, ln_g, ln_b, out);
}

// round 8
// speedup vs baseline: 4.5539x; 1.0526x over previous
#include <cuda_runtime.h>
#include <cuda_bf16.h>
#include <stdint.h>
#include <math.h>

#define Bsz   2
#define Slen  2048
#define Hdim  1024
#define NHn   16
#define HDn   64
#define Mtot  (Bsz*Slen)
#define EPSf  1e-12f

// -------- scratch (no allocations allowed) --------
__device__ float g_y[Mtot*Hdim];
__device__ __nv_bfloat16 g_xhi[Mtot*Hdim], g_xlo[Mtot*Hdim];
__device__ __nv_bfloat16 g_whi[4*Hdim*Hdim], g_wlo[4*Hdim*Hdim];
__device__ __nv_bfloat16 g_qh[Mtot*Hdim], g_ql[Mtot*Hdim];
__device__ __nv_bfloat16 g_kh[Mtot*Hdim], g_kl[Mtot*Hdim];
__device__ __nv_bfloat16 g_vh[Mtot*Hdim], g_vl[Mtot*Hdim];
__device__ __nv_bfloat16 g_ch[Mtot*Hdim], g_cl[Mtot*Hdim];

// ---------------- helpers ----------------
__device__ __forceinline__ uint32_t smem_u32(const void* p) {
    uint32_t a;
    asm("{ .reg .u64 t; cvta.to.shared.u64 t, %1; cvt.u32.u64 %0, t; }" : "=r"(a) : "l"(p));
    return a;
}
__device__ __forceinline__ void cp16(uint32_t dst, const void* src) {
    asm volatile("cp.async.cg.shared.global [%0], [%1], 16;" :: "r"(dst), "l"(src));
}
#define CP_COMMIT() asm volatile("cp.async.commit_group;")
#define CP_WAIT(n)  asm volatile("cp.async.wait_group %0;" :: "n"(n))
#define LDSM_X4(r0,r1,r2,r3,addr) \
    asm volatile("ldmatrix.sync.aligned.m8n8.x4.shared.b16 {%0,%1,%2,%3}, [%4];" \
        : "=r"(r0),"=r"(r1),"=r"(r2),"=r"(r3) : "r"(addr))
#define LDSM_X4_T(r0,r1,r2,r3,addr) \
    asm volatile("ldmatrix.sync.aligned.m8n8.x4.trans.shared.b16 {%0,%1,%2,%3}, [%4];" \
        : "=r"(r0),"=r"(r1),"=r"(r2),"=r"(r3) : "r"(addr))
#define MMA16816(c, a, b) \
    asm volatile("mma.sync.aligned.m16n8k16.row.col.f32.bf16.bf16.f32 " \
        "{%0,%1,%2,%3}, {%4,%5,%6,%7}, {%8,%9}, {%0,%1,%2,%3};" \
        : "+f"((c)[0]),"+f"((c)[1]),"+f"((c)[2]),"+f"((c)[3]) \
        : "r"((a)[0]),"r"((a)[1]),"r"((a)[2]),"r"((a)[3]), "r"((b)[0]),"r"((b)[1]))

__device__ __forceinline__ uint32_t pk_bf16x2(float lo, float hi) {
    uint32_t r;
    asm("cvt.rn.bf16x2.f32 %0, %1, %2;" : "=r"(r) : "f"(hi), "f"(lo));
    return r;
}

// ---------------- split fp32 -> bf16 hi/lo ----------------
__global__ void split_kernel(const float* __restrict__ src, __nv_bfloat16* __restrict__ hi,
                             __nv_bfloat16* __restrict__ lo) {
    int i = blockIdx.x * 256 + threadIdx.x;
    float x = src[i];
    __nv_bfloat16 h = __float2bfloat16(x);
    hi[i] = h;
    lo[i] = __float2bfloat16(x - __bfloat162float(h));
}

// ---------------- GEMM core: cp.async 2-stage pipelined bf16x3 mainloop ----------------
// Dynamic smem: 2 stages x 4 tensors x (128*LDA bf16 = 10240 B) = 81920 B.
#define LDA 40
#define G_TEN 10240
#define G_STG 40960

__device__ __forceinline__ void gemm_core(
    uint32_t sbase,
    const __nv_bfloat16* __restrict__ Ah, const __nv_bfloat16* __restrict__ Al,
    const __nv_bfloat16* __restrict__ Wh, const __nv_bfloat16* __restrict__ Wl,
    int m0, int n0, float acc[4][4][4])
{
    const int tid = threadIdx.x, wid = tid >> 5, lane = tid & 31;
    const int wm0 = (wid & 1) * 64, wn0 = (wid >> 1) * 32;
    const int a_row = wm0 + (lane & 15);
    const int b_row = wn0 + (lane & 7) + ((lane >> 4) * 8);
    const int a_coff = (lane >> 4) * 8;
    const int b_coff = ((lane >> 3) & 1) * 8;

    const int lr = tid >> 2;            // load row helper (two rows per thread via i)
    const int lc = (tid & 3) * 8;

#define G_LOAD(st, k0) do { \
        const uint32_t sb_ = sbase + (st) * G_STG; \
        _Pragma("unroll") \
        for (int i_ = 0; i_ < 2; i_++) { \
            const int r_ = i_ * 64 + lr; \
            const uint32_t off_ = (uint32_t)((r_ * LDA + lc) * 2); \
            const size_t ga_ = (size_t)(m0 + r_) * Hdim + (k0) + lc; \
            const size_t gb_ = (size_t)(n0 + r_) * Hdim + (k0) + lc; \
            cp16(sb_ + off_,              Ah + ga_); \
            cp16(sb_ + G_TEN + off_,      Al + ga_); \
            cp16(sb_ + 2 * G_TEN + off_,  Wh + gb_); \
            cp16(sb_ + 3 * G_TEN + off_,  Wl + gb_); \
        } } while (0)

    G_LOAD(0, 0);
    CP_COMMIT();

    for (int it = 0; it < 32; it++) {
        if (it < 31) {
            G_LOAD((it + 1) & 1, (it + 1) * 32);
            CP_COMMIT();
            CP_WAIT(1);
        } else {
            CP_WAIT(0);
        }
        __syncthreads();

        const uint32_t sb = sbase + (it & 1) * G_STG;
        const uint32_t a_h_base = sb, a_l_base = sb + G_TEN;
        const uint32_t b_h_base = sb + 2 * G_TEN, b_l_base = sb + 3 * G_TEN;

#pragma unroll
        for (int kf = 0; kf < 2; kf++) {
            const int kk = kf * 16;
            uint32_t ah[4][4], al[4][4];
#pragma unroll
            for (int mf = 0; mf < 4; mf++) {
                const uint32_t off = (uint32_t)(((a_row + mf * 16) * LDA + kk + a_coff) * 2);
                LDSM_X4(ah[mf][0], ah[mf][1], ah[mf][2], ah[mf][3], a_h_base + off);
                LDSM_X4(al[mf][0], al[mf][1], al[mf][2], al[mf][3], a_l_base + off);
            }
#pragma unroll
            for (int nfp = 0; nfp < 2; nfp++) {
                const uint32_t off = (uint32_t)(((b_row + nfp * 16) * LDA + kk + b_coff) * 2);
                uint32_t bh[4], bl[4];
                LDSM_X4(bh[0], bh[1], bh[2], bh[3], b_h_base + off);
                LDSM_X4(bl[0], bl[1], bl[2], bl[3], b_l_base + off);
#pragma unroll
                for (int mf = 0; mf < 4; mf++) {
#pragma unroll
                    for (int hf = 0; hf < 2; hf++) {
                        float* c = acc[mf][nfp * 2 + hf];
                        MMA16816(c, ah[mf], bh + hf * 2);
                        MMA16816(c, ah[mf], bl + hf * 2);
                        MMA16816(c, al[mf], bh + hf * 2);
                    }
                }
            }
        }
        __syncthreads();
    }
#undef G_LOAD
}

// ---- fused QKV projection: N stacked 3072, writes bf16 hi/lo head-layout pairs ----
__global__ void __launch_bounds__(256) gemm_qkv(
    const __nv_bfloat16* __restrict__ Ah, const __nv_bfloat16* __restrict__ Al,
    const __nv_bfloat16* __restrict__ Wh, const __nv_bfloat16* __restrict__ Wl,
    const float* __restrict__ bq, const float* __restrict__ bk, const float* __restrict__ bv,
    __nv_bfloat16* __restrict__ qh, __nv_bfloat16* __restrict__ ql,
    __nv_bfloat16* __restrict__ kh, __nv_bfloat16* __restrict__ kl,
    __nv_bfloat16* __restrict__ vh, __nv_bfloat16* __restrict__ vl)
{
    extern __shared__ char dsm[];
    const uint32_t sbase = smem_u32(dsm);
    const int tid = threadIdx.x, wid = tid >> 5, lane = tid & 31;
    const int n0 = blockIdx.x * 128, m0 = blockIdx.y * 128;

    float acc[4][4][4];
#pragma unroll
    for (int i = 0; i < 4; i++)
#pragma unroll
        for (int j = 0; j < 4; j++)
#pragma unroll
            for (int v = 0; v < 4; v++) acc[i][j][v] = 0.f;

    gemm_core(sbase, Ah, Al, Wh, Wl, m0, n0, acc);

    const int proj = n0 >> 10;
    const float* bias = (proj == 0) ? bq : (proj == 1) ? bk : bv;
    __nv_bfloat16* outH = (proj == 0) ? qh : (proj == 1) ? kh : vh;
    __nv_bfloat16* outL = (proj == 0) ? ql : (proj == 1) ? kl : vl;

    const int wm0 = (wid & 1) * 64, wn0 = (wid >> 1) * 32;
    const int rbase = m0 + wm0 + (lane >> 2);
    const int cbase = n0 + wn0 + (lane & 3) * 2;
#pragma unroll
    for (int mf = 0; mf < 4; mf++) {
#pragma unroll
        for (int nf = 0; nf < 4; nf++) {
#pragma unroll
            for (int half = 0; half < 2; half++) {
                const int r = rbase + mf * 16 + half * 8;
                const int c = cbase + nf * 8;
                const int np = c & 1023;
                float v0 = acc[mf][nf][half * 2 + 0] + bias[np];
                float v1 = acc[mf][nf][half * 2 + 1] + bias[np + 1];
                const int b = r >> 11, s = r & (Slen - 1);
                const int h = np >> 6, d = np & 63;
                const size_t idx = (((size_t)(b * NHn + h) * Slen) + s) * HDn + d;
                __nv_bfloat16 h0 = __float2bfloat16(v0);
                __nv_bfloat16 h1 = __float2bfloat16(v1);
                *(uint32_t*)(outH + idx) =
                    ((uint32_t)__bfloat16_as_ushort(h1) << 16) | __bfloat16_as_ushort(h0);
                *(uint32_t*)(outL + idx) =
                    pk_bf16x2(v0 - __bfloat162float(h0), v1 - __bfloat162float(h1));
            }
        }
    }
}

// ---- output projection: fp32 out + bias + residual ----
__global__ void __launch_bounds__(256) gemm_out(
    const __nv_bfloat16* __restrict__ Ah, const __nv_bfloat16* __restrict__ Al,
    const __nv_bfloat16* __restrict__ Wh, const __nv_bfloat16* __restrict__ Wl,
    const float* __restrict__ bias, const float* __restrict__ res, float* __restrict__ out)
{
    extern __shared__ char dsm[];
    const uint32_t sbase = smem_u32(dsm);
    const int tid = threadIdx.x, wid = tid >> 5, lane = tid & 31;
    const int n0 = blockIdx.x * 128, m0 = blockIdx.y * 128;

    float acc[4][4][4];
#pragma unroll
    for (int i = 0; i < 4; i++)
#pragma unroll
        for (int j = 0; j < 4; j++)
#pragma unroll
            for (int v = 0; v < 4; v++) acc[i][j][v] = 0.f;

    gemm_core(sbase, Ah, Al, Wh, Wl, m0, n0, acc);

    const int wm0 = (wid & 1) * 64, wn0 = (wid >> 1) * 32;
    const int rbase = m0 + wm0 + (lane >> 2);
    const int cbase = n0 + wn0 + (lane & 3) * 2;
#pragma unroll
    for (int mf = 0; mf < 4; mf++) {
#pragma unroll
        for (int nf = 0; nf < 4; nf++) {
#pragma unroll
            for (int half = 0; half < 2; half++) {
                const int r = rbase + mf * 16 + half * 8;
                const int c = cbase + nf * 8;
                const size_t idx = (size_t)r * Hdim + c;
                float2 rv = *(const float2*)(res + idx);
                float2 o;
                o.x = acc[mf][nf][half * 2 + 0] + bias[c] + rv.x;
                o.y = acc[mf][nf][half * 2 + 1] + bias[c + 1] + rv.y;
                *(float2*)(out + idx) = o;
            }
        }
    }
}

// ---------------- MMA flash attention (bf16x3), causal, cp.async 2-stage K/V ----------------
// Dynamic smem: 2 stages x 4 tensors x (64*ALD bf16 = 9216 B) = 73728 B.
#define ALD 72
#define A_TEN 9216
#define A_STG 36864
__global__ void __launch_bounds__(128) attn_mma(
    const __nv_bfloat16* __restrict__ Qh, const __nv_bfloat16* __restrict__ Ql,
    const __nv_bfloat16* __restrict__ Kh, const __nv_bfloat16* __restrict__ Kl,
    const __nv_bfloat16* __restrict__ Vh, const __nv_bfloat16* __restrict__ Vl,
    __nv_bfloat16* __restrict__ Ch, __nv_bfloat16* __restrict__ Cl)
{
    extern __shared__ char dsm[];
    const uint32_t sbase = smem_u32(dsm);
    const int tid = threadIdx.x, wid = tid >> 5, lane = tid & 31;
    const int qt = blockIdx.x, h = blockIdx.y, b = blockIdx.z;
    const int m0 = qt * 64, wq0 = wid * 16;
    const size_t base = (size_t)(b * NHn + h) * Slen * HDn;

    // ---- stage Q hi/lo into stage0 Kh/Kl regions (plain stores) ----
    {
        const __nv_bfloat16* srcH = Qh + base + (size_t)m0 * HDn;
        const __nv_bfloat16* srcL = Ql + base + (size_t)m0 * HDn;
#pragma unroll
        for (int i = 0; i < 4; i++) {
            int u = i * 128 + tid, r = u >> 3, c = u & 7;
            int cs = c ^ ((r & 3) << 1);
            int so = (r * ALD + cs * 8) * 2, go = r * 64 + c * 8;
            *(uint4*)(dsm + so) = *(const uint4*)(srcH + go);
            *(uint4*)(dsm + A_TEN + so) = *(const uint4*)(srcL + go);
        }
    }
    __syncthreads();

    const int rA = (lane & 7) + ((lane >> 3) & 1) * 8;
    const int cA = (lane >> 4) & 1;
    const int rB = (lane & 7) + ((lane >> 4) << 3);
    const int cB = (lane >> 3) & 1;
    const int swzA = (rA & 3) << 1;
    const int swzB = (rB & 3) << 1;

    // ---- Q fragments ----
    uint32_t qfh[4][4], qfl[4][4];
    {
        const int row = wq0 + rA;
        const uint32_t rb = (uint32_t)(row * (ALD * 2));
        const int swz = (row & 3) << 1;
#pragma unroll
        for (int kb = 0; kb < 4; kb++) {
            const uint32_t off = rb + (uint32_t)(((2 * kb + cA) ^ swz) * 16);
            LDSM_X4(qfh[kb][0], qfh[kb][1], qfh[kb][2], qfh[kb][3], sbase + off);
            LDSM_X4(qfl[kb][0], qfl[kb][1], qfl[kb][2], qfl[kb][3], sbase + A_TEN + off);
        }
    }
    __syncthreads();

#define A_LOAD(st, k0) do { \
        const uint32_t sb_ = sbase + (st) * A_STG; \
        const __nv_bfloat16* k0p_ = Kh + base + (size_t)(k0) * HDn; \
        const __nv_bfloat16* k1p_ = Kl + base + (size_t)(k0) * HDn; \
        const __nv_bfloat16* v0p_ = Vh + base + (size_t)(k0) * HDn; \
        const __nv_bfloat16* v1p_ = Vl + base + (size_t)(k0) * HDn; \
        _Pragma("unroll") \
        for (int i_ = 0; i_ < 4; i_++) { \
            int u_ = i_ * 128 + tid, r_ = u_ >> 3, c_ = u_ & 7; \
            int cs_ = c_ ^ ((r_ & 3) << 1); \
            uint32_t so_ = (uint32_t)((r_ * ALD + cs_ * 8) * 2); \
            int go_ = r_ * 64 + c_ * 8; \
            cp16(sb_ + so_,             k0p_ + go_); \
            cp16(sb_ + A_TEN + so_,     k1p_ + go_); \
            cp16(sb_ + 2 * A_TEN + so_, v0p_ + go_); \
            cp16(sb_ + 3 * A_TEN + so_, v1p_ + go_); \
        } } while (0)

    A_LOAD(0, 0);
    CP_COMMIT();

    float o[8][4];
#pragma unroll
    for (int i = 0; i < 8; i++)
#pragma unroll
        for (int v = 0; v < 4; v++) o[i][v] = 0.f;
    float mr0 = -1e30f, mr1 = -1e30f, lr0 = 0.f, lr1 = 0.f;

    for (int kt = 0; kt <= qt; kt++) {
        if (kt < qt) {
            A_LOAD((kt + 1) & 1, (kt + 1) * 64);
            CP_COMMIT();
            CP_WAIT(1);
        } else {
            CP_WAIT(0);
        }
        __syncthreads();

        const uint32_t sb = sbase + (kt & 1) * A_STG;
        const uint32_t aKh = sb, aKl = sb + A_TEN;
        const uint32_t aVh = sb + 2 * A_TEN, aVl = sb + 3 * A_TEN;

        // ---- S = Q K^T ----
        float s[8][4];
#pragma unroll
        for (int i = 0; i < 8; i++)
#pragma unroll
            for (int v = 0; v < 4; v++) s[i][v] = 0.f;
#pragma unroll
        for (int kb = 0; kb < 4; kb++) {
#pragma unroll
            for (int np = 0; np < 4; np++) {
                const int row = np * 16 + rB;
                const uint32_t off = (uint32_t)(row * (ALD * 2) + (((2 * kb + cB) ^ swzB)) * 16);
                uint32_t kh[4], kl[4];
                LDSM_X4(kh[0], kh[1], kh[2], kh[3], aKh + off);
                LDSM_X4(kl[0], kl[1], kl[2], kl[3], aKl + off);
                MMA16816(s[2*np],   qfh[kb], kh);     MMA16816(s[2*np],   qfh[kb], kl);
                MMA16816(s[2*np],   qfl[kb], kh);
                MMA16816(s[2*np+1], qfh[kb], kh + 2); MMA16816(s[2*np+1], qfh[kb], kl + 2);
                MMA16816(s[2*np+1], qfl[kb], kh + 2);
            }
        }

#pragma unroll
        for (int nf = 0; nf < 8; nf++)
#pragma unroll
            for (int v = 0; v < 4; v++) s[nf][v] *= 0.125f;
        if (kt == qt) {
            const int row0 = wq0 + (lane >> 2), row1 = row0 + 8;
            const int colb = (lane & 3) * 2;
#pragma unroll
            for (int nf = 0; nf < 8; nf++) {
                const int c0 = nf * 8 + colb, c1 = c0 + 1;
                if (c0 > row0) s[nf][0] = -1e30f;
                if (c1 > row0) s[nf][1] = -1e30f;
                if (c0 > row1) s[nf][2] = -1e30f;
                if (c1 > row1) s[nf][3] = -1e30f;
            }
        }

        // ---- online softmax ----
        float mx0 = s[0][0], mx1 = s[0][2];
#pragma unroll
        for (int nf = 0; nf < 8; nf++) {
            mx0 = fmaxf(mx0, fmaxf(s[nf][0], s[nf][1]));
            mx1 = fmaxf(mx1, fmaxf(s[nf][2], s[nf][3]));
        }
        mx0 = fmaxf(mx0, __shfl_xor_sync(0xffffffffu, mx0, 1));
        mx0 = fmaxf(mx0, __shfl_xor_sync(0xffffffffu, mx0, 2));
        mx1 = fmaxf(mx1, __shfl_xor_sync(0xffffffffu, mx1, 1));
        mx1 = fmaxf(mx1, __shfl_xor_sync(0xffffffffu, mx1, 2));
        const float nm0 = fmaxf(mr0, mx0), nm1 = fmaxf(mr1, mx1);
        const float cr0 = __expf(mr0 - nm0), cr1 = __expf(mr1 - nm1);
        lr0 *= cr0; lr1 *= cr1;
#pragma unroll
        for (int nf = 0; nf < 8; nf++) {
            o[nf][0] *= cr0; o[nf][1] *= cr0;
            o[nf][2] *= cr1; o[nf][3] *= cr1;
        }
        mr0 = nm0; mr1 = nm1;

        uint32_t ph[8], phb[8], pl[8], plb[8];
#pragma unroll
        for (int nf = 0; nf < 8; nf++) {
            float p0 = __expf(s[nf][0] - nm0), p1 = __expf(s[nf][1] - nm0);
            float p2 = __expf(s[nf][2] - nm1), p3 = __expf(s[nf][3] - nm1);
            lr0 += p0 + p1; lr1 += p2 + p3;
            ph[nf]  = pk_bf16x2(p0, p1);
            phb[nf] = pk_bf16x2(p2, p3);
            float h0 = __uint_as_float(ph[nf] << 16);
            float h1 = __uint_as_float(ph[nf] & 0xFFFF0000u);
            float h2 = __uint_as_float(phb[nf] << 16);
            float h3 = __uint_as_float(phb[nf] & 0xFFFF0000u);
            pl[nf]  = pk_bf16x2(p0 - h0, p1 - h1);
            plb[nf] = pk_bf16x2(p2 - h2, p3 - h3);
        }

        // ---- O += P V ----
#pragma unroll
        for (int kb = 0; kb < 4; kb++) {
            uint32_t pah[4] = { ph[2*kb], phb[2*kb], ph[2*kb+1], phb[2*kb+1] };
            uint32_t pal[4] = { pl[2*kb], plb[2*kb], pl[2*kb+1], plb[2*kb+1] };
            const int row = kb * 16 + rA;
            const uint32_t rb = (uint32_t)(row * (ALD * 2));
#pragma unroll
            for (int np = 0; np < 4; np++) {
                const uint32_t off = rb + (uint32_t)(((2 * np + cA) ^ swzA) * 16);
                uint32_t vh[4], vl[4];
                LDSM_X4_T(vh[0], vh[1], vh[2], vh[3], aVh + off);
                LDSM_X4_T(vl[0], vl[1], vl[2], vl[3], aVl + off);
                MMA16816(o[2*np],   pah, vh);     MMA16816(o[2*np],   pah, vl);
                MMA16816(o[2*np],   pal, vh);
                MMA16816(o[2*np+1], pah, vh + 2); MMA16816(o[2*np+1], pah, vl + 2);
                MMA16816(o[2*np+1], pal, vh + 2);
            }
        }
        __syncthreads();
    }
#undef A_LOAD

    lr0 += __shfl_xor_sync(0xffffffffu, lr0, 1);
    lr0 += __shfl_xor_sync(0xffffffffu, lr0, 2);
    lr1 += __shfl_xor_sync(0xffffffffu, lr1, 1);
    lr1 += __shfl_xor_sync(0xffffffffu, lr1, 2);
    const float iv0 = 1.f / lr0, iv1 = 1.f / lr1;

    const int s0 = m0 + wq0 + (lane >> 2), s1 = s0 + 8;
    const size_t rb0 = (size_t)(b * Slen + s0) * Hdim + h * 64;
    const size_t rb1 = (size_t)(b * Slen + s1) * Hdim + h * 64;
#pragma unroll
    for (int nf = 0; nf < 8; nf++) {
        const int col = nf * 8 + (lane & 3) * 2;
        float v0 = o[nf][0] * iv0, v1 = o[nf][1] * iv0;
        float v2 = o[nf][2] * iv1, v3 = o[nf][3] * iv1;
        __nv_bfloat16 h0 = __float2bfloat16(v0), h1 = __float2bfloat16(v1);
        __nv_bfloat16 h2 = __float2bfloat16(v2), h3 = __float2bfloat16(v3);
        *(uint32_t*)(Ch + rb0 + col) =
            ((uint32_t)__bfloat16_as_ushort(h1) << 16) | __bfloat16_as_ushort(h0);
        *(uint32_t*)(Ch + rb1 + col) =
            ((uint32_t)__bfloat16_as_ushort(h3) << 16) | __bfloat16_as_ushort(h2);
        *(uint32_t*)(Cl + rb0 + col) =
            pk_bf16x2(v0 - __bfloat162float(h0), v1 - __bfloat162float(h1));
        *(uint32_t*)(Cl + rb1 + col) =
            pk_bf16x2(v2 - __bfloat162float(h2), v3 - __bfloat162float(h3));
    }
}

// ---------------- LayerNorm ----------------
__global__ void ln_kernel(const float* __restrict__ y, const float* __restrict__ g,
                          const float* __restrict__ be, float* __restrict__ out)
{
    __shared__ float red[256];
    const int row = blockIdx.x, tid = threadIdx.x;
    const float4 v = ((const float4*)(y + (size_t)row * Hdim))[tid];
    float sum = v.x + v.y + v.z + v.w;
    red[tid] = sum; __syncthreads();
    for (int s = 128; s > 0; s >>= 1) { if (tid < s) red[tid] += red[tid + s]; __syncthreads(); }
    const float mu = red[0] * (1.f / 1024.f);
    __syncthreads();
    const float d0 = v.x - mu, d1 = v.y - mu, d2 = v.z - mu, d3 = v.w - mu;
    red[tid] = d0 * d0 + d1 * d1 + d2 * d2 + d3 * d3; __syncthreads();
    for (int s = 128; s > 0; s >>= 1) { if (tid < s) red[tid] += red[tid + s]; __syncthreads(); }
    const float inv = rsqrtf(red[0] * (1.f / 1024.f) + EPSf);
    const float4 gg = ((const float4*)g)[tid];
    const float4 bb = ((const float4*)be)[tid];
    float4 o;
    o.x = d0 * inv * gg.x + bb.x;
    o.y = d1 * inv * gg.y + bb.y;
    o.z = d2 * inv * gg.z + bb.z;
    o.w = d3 * inv * gg.w + bb.w;
    ((float4*)(out + (size_t)row * Hdim))[tid] = o;
}

// ---------------- launch ----------------
extern "C" void kernel_launch(void* const* d_in, const int* in_sizes, int n_in,
                              void* d_out, int out_size)
{
    const float* x    = (const float*)d_in[0];
    const float* Wq   = (const float*)d_in[1];
    const float* bq   = (const float*)d_in[2];
    const float* Wk   = (const float*)d_in[3];
    const float* bk   = (const float*)d_in[4];
    const float* Wv   = (const float*)d_in[5];
    const float* bv   = (const float*)d_in[6];
    const float* Wo   = (const float*)d_in[7];
    const float* bo   = (const float*)d_in[8];
    const float* ln_g = (const float*)d_in[9];
    const float* ln_b = (const float*)d_in[10];
    float* out = (float*)d_out;

    float *yp;
    __nv_bfloat16 *xh, *xl, *wh, *wl, *qh, *ql, *kh, *kl, *vh, *vl, *ch, *cl;
    cudaGetSymbolAddress((void**)&yp, g_y);
    cudaGetSymbolAddress((void**)&xh, g_xhi);
    cudaGetSymbolAddress((void**)&xl, g_xlo);
    cudaGetSymbolAddress((void**)&wh, g_whi);
    cudaGetSymbolAddress((void**)&wl, g_wlo);
    cudaGetSymbolAddress((void**)&qh, g_qh);
    cudaGetSymbolAddress((void**)&ql, g_ql);
    cudaGetSymbolAddress((void**)&kh, g_kh);
    cudaGetSymbolAddress((void**)&kl, g_kl);
    cudaGetSymbolAddress((void**)&vh, g_vh);
    cudaGetSymbolAddress((void**)&vl, g_vl);
    cudaGetSymbolAddress((void**)&ch, g_ch);
    cudaGetSymbolAddress((void**)&cl, g_cl);

    static bool attr_done = false;
    if (!attr_done) {
        cudaFuncSetAttribute(gemm_qkv, cudaFuncAttributeMaxDynamicSharedMemorySize, 2 * G_STG);
        cudaFuncSetAttribute(gemm_out, cudaFuncAttributeMaxDynamicSharedMemorySize, 2 * G_STG);
        cudaFuncSetAttribute(attn_mma, cudaFuncAttributeMaxDynamicSharedMemorySize, 2 * A_STG);
        attr_done = true;
    }

    const int WSZ = Hdim * Hdim;
    split_kernel<<<Mtot * Hdim / 256, 256>>>(x, xh, xl);
    split_kernel<<<WSZ / 256, 256>>>(Wq, wh + 0 * WSZ, wl + 0 * WSZ);
    split_kernel<<<WSZ / 256, 256>>>(Wk, wh + 1 * WSZ, wl + 1 * WSZ);
    split_kernel<<<WSZ / 256, 256>>>(Wv, wh + 2 * WSZ, wl + 2 * WSZ);
    split_kernel<<<WSZ / 256, 256>>>(Wo, wh + 3 * WSZ, wl + 3 * WSZ);

    gemm_qkv<<<dim3(3 * Hdim / 128, Mtot / 128), 256, 2 * G_STG>>>(
        xh, xl, wh, wl, bq, bk, bv, qh, ql, kh, kl, vh, vl);

    attn_mma<<<dim3(Slen / 64, NHn, Bsz), 128, 2 * A_STG>>>(qh, ql, kh, kl, vh, vl, ch, cl);

    gemm_out<<<dim3(Hdim / 128, Mtot / 128), 256, 2 * G_STG>>>(
        ch, cl, wh + 3 * WSZ, wl + 3 * WSZ, bo, x, yp);

    ln_kernel<<<Mtot, 256>>>(yp, ln_g, ln_b, out);
}